// round 1
// baseline (speedup 1.0000x reference)
#include <cuda_runtime.h>
#include <cuda_bf16.h>

// Shapes (fixed by the problem)
#define B_   16
#define N_   64
#define C_   128
#define H_   64
#define W_   64
#define HW_  (H_ * W_)
#define NROI (B_ * N_)
#define OUTC 256
#define MAXG 16

// Scratch: z transposed to [B, H, W, C] and pooled features [NROI, C]
__device__ float g_zf[(size_t)B_ * HW_ * C_];     // 32 MB
__device__ float g_feats[NROI * C_];              // 512 KB

// ---------------------------------------------------------------------------
// Kernel 1: transpose z [B, C, HW] -> zf [B, HW, C]
// ---------------------------------------------------------------------------
__global__ void transpose_kernel(const float* __restrict__ z) {
    __shared__ float tile[32][33];
    int b   = blockIdx.z;
    int hw0 = blockIdx.x * 32;
    int c0  = blockIdx.y * 32;
    const float* zb  = z    + (size_t)b * C_ * HW_;
    float*       zfb = g_zf + (size_t)b * HW_ * C_;

    #pragma unroll
    for (int i = threadIdx.y; i < 32; i += 8)
        tile[i][threadIdx.x] = zb[(size_t)(c0 + i) * HW_ + hw0 + threadIdx.x];
    __syncthreads();
    #pragma unroll
    for (int i = threadIdx.y; i < 32; i += 8)
        zfb[(size_t)(hw0 + i) * C_ + c0 + threadIdx.x] = tile[threadIdx.x][i];
}

// ---------------------------------------------------------------------------
// Kernel 2: ROI-align (output 1x1, aligned=True, adaptive sampling_ratio)
// One block per ROI, one thread per channel.
// ---------------------------------------------------------------------------
__global__ void __launch_bounds__(128) roi_kernel(const float* __restrict__ bboxes) {
    int roi = blockIdx.x;           // 0..1023
    int b   = roi >> 6;             // / N_
    int c   = threadIdx.x;          // channel

    float4 box = reinterpret_cast<const float4*>(bboxes)[roi];
    // *0.125 is exact (power of two), so fmaf == (mul then add) bitwise
    float x1 = box.x * 0.125f - 0.5f;
    float y1 = box.y * 0.125f - 0.5f;
    float x2 = box.z * 0.125f - 0.5f;
    float y2 = box.w * 0.125f - 0.5f;

    float roi_w = x2 - x1, roi_h = y2 - y1;
    float gwf = fminf(fmaxf(ceilf(roi_w), 1.0f), (float)MAXG);
    float ghf = fminf(fmaxf(ceilf(roi_h), 1.0f), (float)MAXG);
    int gw = (int)gwf, gh = (int)ghf;
    float bw = roi_w / gwf, bh = roi_h / ghf;

    const float* zb = g_zf + (size_t)b * HW_ * C_;

    float acc = 0.0f;
    for (int iy = 0; iy < gh; ++iy) {
        float sy = y1 + ((float)iy + 0.5f) * bh;
        if (!(sy > -1.0f && sy < (float)H_)) continue;   // out-of-range -> 0 contribution
        float cy = fmaxf(sy, 0.0f);
        int yl = min((int)floorf(cy), H_ - 1);
        int yh = min(yl + 1, H_ - 1);
        float fy = (yl >= H_ - 1) ? 0.0f : (cy - (float)yl);
        float hy = 1.0f - fy;
        const float* rl = zb + (size_t)yl * (W_ * C_);
        const float* rh = zb + (size_t)yh * (W_ * C_);

        for (int ix = 0; ix < gw; ++ix) {
            float sx = x1 + ((float)ix + 0.5f) * bw;
            if (!(sx > -1.0f && sx < (float)W_)) continue;
            float cx = fmaxf(sx, 0.0f);
            int xl = min((int)floorf(cx), W_ - 1);
            int xh = min(xl + 1, W_ - 1);
            float fx = (xl >= W_ - 1) ? 0.0f : (cx - (float)xl);
            float hx = 1.0f - fx;

            float v11 = rl[xl * C_ + c];
            float v12 = rl[xh * C_ + c];
            float v21 = rh[xl * C_ + c];
            float v22 = rh[xh * C_ + c];
            acc += (hy * hx) * v11 + (hy * fx) * v12
                 + (fy * hx) * v21 + (fy * fx) * v22;
        }
    }
    g_feats[roi * C_ + c] = acc / (gwf * ghf);
}

// ---------------------------------------------------------------------------
// Kernel 3: out[m, o] = feats[m, :] . W[o, :] + b[o]
// 64 blocks x 16 rows; 256 threads, one output column per thread.
// W staged through smem TRANSPOSED (padded 257) -> conflict-free inner reads.
// ---------------------------------------------------------------------------
#define MT 16
__global__ void __launch_bounds__(256) gemm_kernel(const float* __restrict__ Wm,
                                                   const float* __restrict__ bvec,
                                                   float* __restrict__ out) {
    __shared__ float fsm[MT][C_];       // 8 KB
    __shared__ float Wt[32][257];       // ~33 KB, padded

    int m0  = blockIdx.x * MT;
    int tid = threadIdx.x;
    int o   = tid;

    // load feats tile (coalesced)
    for (int i = tid; i < MT * C_; i += 256)
        fsm[i >> 7][i & 127] = g_feats[m0 * C_ + i];

    float acc[MT];
    #pragma unroll
    for (int m = 0; m < MT; ++m) acc[m] = 0.0f;

    for (int kc = 0; kc < 4; ++kc) {
        __syncthreads();
        // stage W chunk [256 outputs][32 k] transposed into Wt[k][o]
        // consecutive tid -> consecutive kk -> consecutive gmem addrs (coalesced)
        // and consecutive smem banks (padded stride 257).
        for (int j = tid; j < 256 * 32; j += 256) {
            int oo = j >> 5, kk = j & 31;
            Wt[kk][oo] = Wm[oo * C_ + kc * 32 + kk];
        }
        __syncthreads();
        #pragma unroll
        for (int kk = 0; kk < 32; ++kk) {
            float w = Wt[kk][o];            // conflict-free: lanes hit distinct banks
            int k = kc * 32 + kk;
            #pragma unroll
            for (int m = 0; m < MT; ++m)
                acc[m] += fsm[m][k] * w;    // fsm: warp-broadcast
        }
    }

    float bo = bvec[o];
    #pragma unroll
    for (int m = 0; m < MT; ++m)
        out[(size_t)(m0 + m) * OUTC + o] = acc[m] + bo;
}

// ---------------------------------------------------------------------------
extern "C" void kernel_launch(void* const* d_in, const int* in_sizes, int n_in,
                              void* d_out, int out_size) {
    const float* z      = (const float*)d_in[0];   // [B,C,H,W]
    const float* bboxes = (const float*)d_in[1];   // [B,N,4]
    const float* Wm     = (const float*)d_in[2];   // [OUTC,C]
    const float* bvec   = (const float*)d_in[3];   // [OUTC]
    float* out = (float*)d_out;                    // [B,N,OUTC]

    dim3 tgrid(HW_ / 32, C_ / 32, B_);             // (128, 4, 16)
    transpose_kernel<<<tgrid, dim3(32, 8)>>>(z);
    roi_kernel<<<NROI, 128>>>(bboxes);
    gemm_kernel<<<NROI / MT, 256>>>(Wm, bvec, out);
}

// round 2
// speedup vs baseline: 1.6547x; 1.6547x over previous
#include <cuda_runtime.h>
#include <cuda_bf16.h>

// Shapes (fixed by the problem)
#define B_   16
#define N_   64
#define C_   128
#define H_   64
#define W_   64
#define HW_  (H_ * W_)
#define NROI (B_ * N_)
#define OUTC 256
#define MAXG 16

// Scratch: z transposed to [B, H, W, C] and pooled features [NROI, C]
__device__ float g_zf[(size_t)B_ * HW_ * C_];     // 32 MB
__device__ float g_feats[NROI * C_];              // 512 KB

// ---------------------------------------------------------------------------
// Kernel 1: transpose z [B, C, HW] -> zf [B, HW, C]
// Tile: 32 channels x 128 hw per block. Fully vectorized gmem (LDG.128 /
// STG.128), conflict-free smem both directions:
//   - load lane map: 4 rows x 8 float4-cols per warp -> 4x128B gmem segments,
//     STS banks (row + 4*col4 + i) mod 32 cover all 32 banks.
//   - store: lanes read 4 consecutive rows at same hw; [32][129] pad makes
//     banks (c + hw) mod 32 distinct.
// ---------------------------------------------------------------------------
__global__ void __launch_bounds__(256) transpose_kernel(const float* __restrict__ z) {
    __shared__ float tile[32][129];
    int b   = blockIdx.z;
    int hw0 = blockIdx.x * 128;
    int c0  = blockIdx.y * 32;
    const float* zb  = z    + (size_t)b * C_ * HW_;
    float*       zfb = g_zf + (size_t)b * HW_ * C_;
    int t = threadIdx.x;

    #pragma unroll
    for (int it = 0; it < 4; ++it) {
        int j    = t + 256 * it;
        int row  = ((j >> 5) & 7) * 4 + ((j >> 3) & 3);   // 0..31 (channel)
        int col4 = ((j >> 8) & 3) * 8 + (j & 7);          // 0..31 (hw/4)
        float4 v = *(const float4*)(zb + (size_t)(c0 + row) * HW_ + hw0 + col4 * 4);
        tile[row][col4 * 4 + 0] = v.x;
        tile[row][col4 * 4 + 1] = v.y;
        tile[row][col4 * 4 + 2] = v.z;
        tile[row][col4 * 4 + 3] = v.w;
    }
    __syncthreads();
    #pragma unroll
    for (int it = 0; it < 4; ++it) {
        int j  = t + 256 * it;
        int hw = j >> 3;          // 0..127
        int cq = j & 7;           // 0..7 (channel/4)
        float4 v;
        v.x = tile[cq * 4 + 0][hw];
        v.y = tile[cq * 4 + 1][hw];
        v.z = tile[cq * 4 + 2][hw];
        v.w = tile[cq * 4 + 3][hw];
        *(float4*)(zfb + (size_t)(hw0 + hw) * C_ + c0 + cq * 4) = v;
    }
}

// ---------------------------------------------------------------------------
// Kernel 2: ROI-align (output 1x1, aligned=True, adaptive sampling_ratio)
// One block per ROI; (128 channels x 4 sample-slices) = 512 threads.
// Each slice handles iy = ys, ys+4, ...; shared-mem reduce across slices.
// ---------------------------------------------------------------------------
__global__ void __launch_bounds__(512) roi_kernel(const float* __restrict__ bboxes) {
    int roi = blockIdx.x;           // 0..1023
    int b   = roi >> 6;             // / N_
    int c   = threadIdx.x;          // channel 0..127
    int ys  = threadIdx.y;          // sample slice 0..3

    float4 box = reinterpret_cast<const float4*>(bboxes)[roi];
    float x1 = box.x * 0.125f - 0.5f;
    float y1 = box.y * 0.125f - 0.5f;
    float x2 = box.z * 0.125f - 0.5f;
    float y2 = box.w * 0.125f - 0.5f;

    float roi_w = x2 - x1, roi_h = y2 - y1;
    float gwf = fminf(fmaxf(ceilf(roi_w), 1.0f), (float)MAXG);
    float ghf = fminf(fmaxf(ceilf(roi_h), 1.0f), (float)MAXG);
    int gw = (int)gwf, gh = (int)ghf;
    float bw = roi_w / gwf, bh = roi_h / ghf;

    const float* zb = g_zf + (size_t)b * HW_ * C_;

    float acc = 0.0f;
    for (int iy = ys; iy < gh; iy += 4) {
        float sy = y1 + ((float)iy + 0.5f) * bh;
        if (!(sy > -1.0f && sy < (float)H_)) continue;   // out-of-range -> 0
        float cy = fmaxf(sy, 0.0f);
        int yl = min((int)floorf(cy), H_ - 1);
        int yh = min(yl + 1, H_ - 1);
        float fy = (yl >= H_ - 1) ? 0.0f : (cy - (float)yl);
        float hy = 1.0f - fy;
        const float* rl = zb + (size_t)yl * (W_ * C_);
        const float* rh = zb + (size_t)yh * (W_ * C_);

        #pragma unroll 2
        for (int ix = 0; ix < gw; ++ix) {
            float sx = x1 + ((float)ix + 0.5f) * bw;
            if (!(sx > -1.0f && sx < (float)W_)) continue;
            float cx = fmaxf(sx, 0.0f);
            int xl = min((int)floorf(cx), W_ - 1);
            int xh = min(xl + 1, W_ - 1);
            float fx = (xl >= W_ - 1) ? 0.0f : (cx - (float)xl);
            float hx = 1.0f - fx;

            float v11 = rl[xl * C_ + c];
            float v12 = rl[xh * C_ + c];
            float v21 = rh[xl * C_ + c];
            float v22 = rh[xh * C_ + c];
            acc += (hy * hx) * v11 + (hy * fx) * v12
                 + (fy * hx) * v21 + (fy * fx) * v22;
        }
    }

    __shared__ float red[4][C_];
    red[ys][c] = acc;
    __syncthreads();
    if (ys == 0) {
        float s = red[0][c] + red[1][c] + red[2][c] + red[3][c];
        g_feats[roi * C_ + c] = s / (gwf * ghf);
    }
}

// ---------------------------------------------------------------------------
// Kernel 3: out[m, o] = feats[m, :] . W[o, :] + b[o]
// 128 blocks x 8 rows; 256 threads, one output column per thread.
// W staged through smem TRANSPOSED (padded 257) -> conflict-free inner reads.
// ---------------------------------------------------------------------------
#define MT 8
__global__ void __launch_bounds__(256) gemm_kernel(const float* __restrict__ Wm,
                                                   const float* __restrict__ bvec,
                                                   float* __restrict__ out) {
    __shared__ float fsm[MT][C_];       // 4 KB
    __shared__ float Wt[32][257];       // ~33 KB, padded

    int m0  = blockIdx.x * MT;
    int tid = threadIdx.x;
    int o   = tid;

    // load feats tile (coalesced)
    for (int i = tid; i < MT * C_; i += 256)
        fsm[i >> 7][i & 127] = g_feats[m0 * C_ + i];

    float acc[MT];
    #pragma unroll
    for (int m = 0; m < MT; ++m) acc[m] = 0.0f;

    for (int kc = 0; kc < 4; ++kc) {
        __syncthreads();
        // stage W chunk [256 outputs][32 k] transposed into Wt[k][o]
        for (int j = tid; j < 256 * 32; j += 256) {
            int oo = j >> 5, kk = j & 31;
            Wt[kk][oo] = Wm[oo * C_ + kc * 32 + kk];
        }
        __syncthreads();
        #pragma unroll
        for (int kk = 0; kk < 32; ++kk) {
            float w = Wt[kk][o];            // conflict-free
            int k = kc * 32 + kk;
            #pragma unroll
            for (int m = 0; m < MT; ++m)
                acc[m] += fsm[m][k] * w;    // warp-broadcast
        }
    }

    float bo = bvec[o];
    #pragma unroll
    for (int m = 0; m < MT; ++m)
        out[(size_t)(m0 + m) * OUTC + o] = acc[m] + bo;
}

// ---------------------------------------------------------------------------
extern "C" void kernel_launch(void* const* d_in, const int* in_sizes, int n_in,
                              void* d_out, int out_size) {
    const float* z      = (const float*)d_in[0];   // [B,C,H,W]
    const float* bboxes = (const float*)d_in[1];   // [B,N,4]
    const float* Wm     = (const float*)d_in[2];   // [OUTC,C]
    const float* bvec   = (const float*)d_in[3];   // [OUTC]
    float* out = (float*)d_out;                    // [B,N,OUTC]

    dim3 tgrid(HW_ / 128, C_ / 32, B_);            // (32, 4, 16)
    transpose_kernel<<<tgrid, 256>>>(z);
    roi_kernel<<<NROI, dim3(128, 4)>>>(bboxes);
    gemm_kernel<<<NROI / MT, 256>>>(Wm, bvec, out);
}

// round 3
// speedup vs baseline: 2.0622x; 1.2463x over previous
#include <cuda_runtime.h>
#include <cuda_bf16.h>

// Shapes (fixed by the problem)
#define B_   16
#define N_   64
#define C_   128
#define H_   64
#define W_   64
#define HW_  (H_ * W_)
#define NROI (B_ * N_)
#define OUTC 256
#define MAXG 16

// Scratch: z transposed to [B, H, W, C] and pooled features [NROI, C]
__device__ float g_zf[(size_t)B_ * HW_ * C_];     // 32 MB
__device__ float g_feats[NROI * C_];              // 512 KB

// ---------------------------------------------------------------------------
// Kernel 0: zero feats accumulator (128K floats)
// ---------------------------------------------------------------------------
__global__ void zero_feats_kernel() {
    int i = blockIdx.x * 256 + threadIdx.x;        // 128 blocks x 256 thr x float4
    reinterpret_cast<float4*>(g_feats)[i] = make_float4(0.f, 0.f, 0.f, 0.f);
}

// ---------------------------------------------------------------------------
// Kernel 1: transpose z [B, C, HW] -> zf [B, HW, C]  (vectorized both sides)
// ---------------------------------------------------------------------------
__global__ void __launch_bounds__(256) transpose_kernel(const float* __restrict__ z) {
    __shared__ float tile[32][129];
    int b   = blockIdx.z;
    int hw0 = blockIdx.x * 128;
    int c0  = blockIdx.y * 32;
    const float* zb  = z    + (size_t)b * C_ * HW_;
    float*       zfb = g_zf + (size_t)b * HW_ * C_;
    int t = threadIdx.x;

    #pragma unroll
    for (int it = 0; it < 4; ++it) {
        int j    = t + 256 * it;
        int row  = ((j >> 5) & 7) * 4 + ((j >> 3) & 3);   // 0..31 (channel)
        int col4 = ((j >> 8) & 3) * 8 + (j & 7);          // 0..31 (hw/4)
        float4 v = *(const float4*)(zb + (size_t)(c0 + row) * HW_ + hw0 + col4 * 4);
        tile[row][col4 * 4 + 0] = v.x;
        tile[row][col4 * 4 + 1] = v.y;
        tile[row][col4 * 4 + 2] = v.z;
        tile[row][col4 * 4 + 3] = v.w;
    }
    __syncthreads();
    #pragma unroll
    for (int it = 0; it < 4; ++it) {
        int j  = t + 256 * it;
        int hw = j >> 3;          // 0..127
        int cq = j & 7;           // 0..7 (channel/4)
        float4 v;
        v.x = tile[cq * 4 + 0][hw];
        v.y = tile[cq * 4 + 1][hw];
        v.z = tile[cq * 4 + 2][hw];
        v.w = tile[cq * 4 + 3][hw];
        *(float4*)(zfb + (size_t)(hw0 + hw) * C_ + c0 + cq * 4) = v;
    }
}

// ---------------------------------------------------------------------------
// Kernel 2: ROI-align, one block per (roi, iy sample-row).
// Blocks with iy >= gh (or out-of-range sy) exit. 128 threads = channels.
// Partial row sums (pre-scaled by 1/(gh*gw)) accumulated via atomicAdd.
// ---------------------------------------------------------------------------
__global__ void __launch_bounds__(128) roi_kernel(const float* __restrict__ bboxes) {
    int roi = blockIdx.x;           // 0..1023
    int iy  = blockIdx.y;           // 0..15
    int b   = roi >> 6;
    int c   = threadIdx.x;

    float4 box = reinterpret_cast<const float4*>(bboxes)[roi];
    float x1 = box.x * 0.125f - 0.5f;
    float y1 = box.y * 0.125f - 0.5f;
    float x2 = box.z * 0.125f - 0.5f;
    float y2 = box.w * 0.125f - 0.5f;

    float roi_w = x2 - x1, roi_h = y2 - y1;
    float gwf = fminf(fmaxf(ceilf(roi_w), 1.0f), (float)MAXG);
    float ghf = fminf(fmaxf(ceilf(roi_h), 1.0f), (float)MAXG);
    int gw = (int)gwf, gh = (int)ghf;
    if (iy >= gh) return;

    float bw = roi_w / gwf, bh = roi_h / ghf;

    float sy = y1 + ((float)iy + 0.5f) * bh;
    if (!(sy > -1.0f && sy < (float)H_)) return;     // whole row contributes 0
    float cy = fmaxf(sy, 0.0f);
    int yl = min((int)floorf(cy), H_ - 1);
    int yh = min(yl + 1, H_ - 1);
    float fy = (yl >= H_ - 1) ? 0.0f : (cy - (float)yl);
    float hy = 1.0f - fy;

    const float* zb = g_zf + (size_t)b * HW_ * C_;
    const float* rl = zb + (size_t)yl * (W_ * C_);
    const float* rh = zb + (size_t)yh * (W_ * C_);

    float acc = 0.0f;
    #pragma unroll 4
    for (int ix = 0; ix < gw; ++ix) {
        float sx = x1 + ((float)ix + 0.5f) * bw;
        if (!(sx > -1.0f && sx < (float)W_)) continue;
        float cx = fmaxf(sx, 0.0f);
        int xl = min((int)floorf(cx), W_ - 1);
        int xh = min(xl + 1, W_ - 1);
        float fx = (xl >= W_ - 1) ? 0.0f : (cx - (float)xl);
        float hx = 1.0f - fx;

        float v11 = rl[xl * C_ + c];
        float v12 = rl[xh * C_ + c];
        float v21 = rh[xl * C_ + c];
        float v22 = rh[xh * C_ + c];
        acc += (hy * hx) * v11 + (hy * fx) * v12
             + (fy * hx) * v21 + (fy * fx) * v22;
    }

    atomicAdd(&g_feats[roi * C_ + c], acc * (1.0f / (gwf * ghf)));
}

// ---------------------------------------------------------------------------
// Kernel 3: out[m, o] = feats[m, :] . W[o, :] + b[o]
// ---------------------------------------------------------------------------
#define MT 8
__global__ void __launch_bounds__(256) gemm_kernel(const float* __restrict__ Wm,
                                                   const float* __restrict__ bvec,
                                                   float* __restrict__ out) {
    __shared__ float fsm[MT][C_];       // 4 KB
    __shared__ float Wt[32][257];       // ~33 KB, padded

    int m0  = blockIdx.x * MT;
    int tid = threadIdx.x;
    int o   = tid;

    for (int i = tid; i < MT * C_; i += 256)
        fsm[i >> 7][i & 127] = g_feats[m0 * C_ + i];

    float acc[MT];
    #pragma unroll
    for (int m = 0; m < MT; ++m) acc[m] = 0.0f;

    for (int kc = 0; kc < 4; ++kc) {
        __syncthreads();
        for (int j = tid; j < 256 * 32; j += 256) {
            int oo = j >> 5, kk = j & 31;
            Wt[kk][oo] = Wm[oo * C_ + kc * 32 + kk];
        }
        __syncthreads();
        #pragma unroll
        for (int kk = 0; kk < 32; ++kk) {
            float w = Wt[kk][o];            // conflict-free
            int k = kc * 32 + kk;
            #pragma unroll
            for (int m = 0; m < MT; ++m)
                acc[m] += fsm[m][k] * w;    // warp-broadcast
        }
    }

    float bo = bvec[o];
    #pragma unroll
    for (int m = 0; m < MT; ++m)
        out[(size_t)(m0 + m) * OUTC + o] = acc[m] + bo;
}

// ---------------------------------------------------------------------------
extern "C" void kernel_launch(void* const* d_in, const int* in_sizes, int n_in,
                              void* d_out, int out_size) {
    const float* z      = (const float*)d_in[0];   // [B,C,H,W]
    const float* bboxes = (const float*)d_in[1];   // [B,N,4]
    const float* Wm     = (const float*)d_in[2];   // [OUTC,C]
    const float* bvec   = (const float*)d_in[3];   // [OUTC]
    float* out = (float*)d_out;                    // [B,N,OUTC]

    zero_feats_kernel<<<NROI * C_ / (256 * 4), 256>>>();
    dim3 tgrid(HW_ / 128, C_ / 32, B_);            // (32, 4, 16)
    transpose_kernel<<<tgrid, 256>>>(z);
    roi_kernel<<<dim3(NROI, MAXG), 128>>>(bboxes);
    gemm_kernel<<<NROI / MT, 256>>>(Wm, bvec, out);
}

// round 4
// speedup vs baseline: 2.2593x; 1.0956x over previous
#include <cuda_runtime.h>
#include <cuda_bf16.h>

// Shapes (fixed by the problem)
#define B_   16
#define N_   64
#define C_   128
#define H_   64
#define W_   64
#define HW_  (H_ * W_)
#define NROI (B_ * N_)
#define OUTC 256
#define MAXG 16

// Scratch: z transposed to [B, H, W, C] and pooled features [NROI, C]
__device__ float g_zf[(size_t)B_ * HW_ * C_];     // 32 MB
__device__ float g_feats[NROI * C_];              // 512 KB

// ---------------------------------------------------------------------------
// Kernel 0: zero feats accumulator (128K floats)
// ---------------------------------------------------------------------------
__global__ void zero_feats_kernel() {
    int i = blockIdx.x * 256 + threadIdx.x;
    reinterpret_cast<float4*>(g_feats)[i] = make_float4(0.f, 0.f, 0.f, 0.f);
}

// ---------------------------------------------------------------------------
// Kernel 1: transpose z [B, C, HW] -> zf [B, HW, C]  (vectorized both sides)
// ---------------------------------------------------------------------------
__global__ void __launch_bounds__(256) transpose_kernel(const float* __restrict__ z) {
    __shared__ float tile[32][129];
    int b   = blockIdx.z;
    int hw0 = blockIdx.x * 128;
    int c0  = blockIdx.y * 32;
    const float* zb  = z    + (size_t)b * C_ * HW_;
    float*       zfb = g_zf + (size_t)b * HW_ * C_;
    int t = threadIdx.x;

    #pragma unroll
    for (int it = 0; it < 4; ++it) {
        int j    = t + 256 * it;
        int row  = ((j >> 5) & 7) * 4 + ((j >> 3) & 3);   // 0..31 (channel)
        int col4 = ((j >> 8) & 3) * 8 + (j & 7);          // 0..31 (hw/4)
        float4 v = *(const float4*)(zb + (size_t)(c0 + row) * HW_ + hw0 + col4 * 4);
        tile[row][col4 * 4 + 0] = v.x;
        tile[row][col4 * 4 + 1] = v.y;
        tile[row][col4 * 4 + 2] = v.z;
        tile[row][col4 * 4 + 3] = v.w;
    }
    __syncthreads();
    #pragma unroll
    for (int it = 0; it < 4; ++it) {
        int j  = t + 256 * it;
        int hw = j >> 3;          // 0..127
        int cq = j & 7;           // 0..7 (channel/4)
        float4 v;
        v.x = tile[cq * 4 + 0][hw];
        v.y = tile[cq * 4 + 1][hw];
        v.z = tile[cq * 4 + 2][hw];
        v.w = tile[cq * 4 + 3][hw];
        *(float4*)(zfb + (size_t)(hw0 + hw) * C_ + c0 + cq * 4) = v;
    }
}

// ---------------------------------------------------------------------------
// Kernel 2: ROI-align, one block per (roi, iy sample-row).
// ---------------------------------------------------------------------------
__global__ void __launch_bounds__(128) roi_kernel(const float* __restrict__ bboxes) {
    int roi = blockIdx.x;           // 0..1023
    int iy  = blockIdx.y;           // 0..15
    int b   = roi >> 6;
    int c   = threadIdx.x;

    float4 box = reinterpret_cast<const float4*>(bboxes)[roi];
    float x1 = box.x * 0.125f - 0.5f;
    float y1 = box.y * 0.125f - 0.5f;
    float x2 = box.z * 0.125f - 0.5f;
    float y2 = box.w * 0.125f - 0.5f;

    float roi_w = x2 - x1, roi_h = y2 - y1;
    float gwf = fminf(fmaxf(ceilf(roi_w), 1.0f), (float)MAXG);
    float ghf = fminf(fmaxf(ceilf(roi_h), 1.0f), (float)MAXG);
    int gw = (int)gwf, gh = (int)ghf;
    if (iy >= gh) return;

    float bw = roi_w / gwf, bh = roi_h / ghf;

    float sy = y1 + ((float)iy + 0.5f) * bh;
    if (!(sy > -1.0f && sy < (float)H_)) return;     // whole row contributes 0
    float cy = fmaxf(sy, 0.0f);
    int yl = min((int)floorf(cy), H_ - 1);
    int yh = min(yl + 1, H_ - 1);
    float fy = (yl >= H_ - 1) ? 0.0f : (cy - (float)yl);
    float hy = 1.0f - fy;

    const float* zb = g_zf + (size_t)b * HW_ * C_;
    const float* rl = zb + (size_t)yl * (W_ * C_);
    const float* rh = zb + (size_t)yh * (W_ * C_);

    float acc = 0.0f;
    #pragma unroll 4
    for (int ix = 0; ix < gw; ++ix) {
        float sx = x1 + ((float)ix + 0.5f) * bw;
        if (!(sx > -1.0f && sx < (float)W_)) continue;
        float cx = fmaxf(sx, 0.0f);
        int xl = min((int)floorf(cx), W_ - 1);
        int xh = min(xl + 1, W_ - 1);
        float fx = (xl >= W_ - 1) ? 0.0f : (cx - (float)xl);
        float hx = 1.0f - fx;

        float v11 = rl[xl * C_ + c];
        float v12 = rl[xh * C_ + c];
        float v21 = rh[xl * C_ + c];
        float v22 = rh[xh * C_ + c];
        acc += (hy * hx) * v11 + (hy * fx) * v12
             + (fy * hx) * v21 + (fy * fx) * v22;
    }

    atomicAdd(&g_feats[roi * C_ + c], acc * (1.0f / (gwf * ghf)));
}

// ---------------------------------------------------------------------------
// Kernel 3: out[m, o] = feats[m, :] . W[o, :] + b[o]
// Register-tiled GEMM: block tile 16m x 64o, thread tile 2m x 2o,
// 256 threads, grid (64, 4) = 256 blocks.
//   Wt[k][o]  (pad 68): staged with lanes spanning o  -> conflict-free STS;
//                       compute LDS.64 spans 64 words -> conflict-free.
//   fsmT[k][m]: transposed feats -> broadcast float2 per warp in k-loop.
// ---------------------------------------------------------------------------
#define MT 16
#define OT 64
__global__ void __launch_bounds__(256) gemm_kernel(const float* __restrict__ Wm,
                                                   const float* __restrict__ bvec,
                                                   float* __restrict__ out) {
    __shared__ float Wt[C_][OT + 4];     // [128][68] ~34 KB
    __shared__ float fsmT[C_][MT];       // [128][16]   8 KB

    int m0  = blockIdx.x * MT;
    int o0  = blockIdx.y * OT;
    int tid = threadIdx.x;

    // Stage W slice [OT][C] -> Wt[k][o]. Lanes span o (conflict-free STS);
    // gmem reads are 16B/lane at 512B stride (L2 sectors, slice is tiny).
    #pragma unroll
    for (int it = 0; it < (OT * C_ / 4) / 256; ++it) {   // 8 iters
        int idx = tid + 256 * it;
        int o   = idx & (OT - 1);
        int k4  = idx >> 6;                               // 0..31
        float4 v = *(const float4*)(Wm + (size_t)(o0 + o) * C_ + k4 * 4);
        Wt[k4 * 4 + 0][o] = v.x;
        Wt[k4 * 4 + 1][o] = v.y;
        Wt[k4 * 4 + 2][o] = v.z;
        Wt[k4 * 4 + 3][o] = v.w;
    }
    // Stage feats [MT][C] -> fsmT[k][m].
    #pragma unroll
    for (int it = 0; it < (MT * C_ / 4) / 256; ++it) {    // 2 iters
        int idx = tid + 256 * it;
        int m   = idx & (MT - 1);
        int k4  = idx >> 4;                               // 0..31
        float4 v = *(const float4*)(g_feats + (size_t)(m0 + m) * C_ + k4 * 4);
        fsmT[k4 * 4 + 0][m] = v.x;
        fsmT[k4 * 4 + 1][m] = v.y;
        fsmT[k4 * 4 + 2][m] = v.z;
        fsmT[k4 * 4 + 3][m] = v.w;
    }
    __syncthreads();

    int oq = tid & 31;        // o-pair index 0..31
    int mq = tid >> 5;        // m-pair index 0..7 (warp-constant)

    float acc00 = 0.f, acc01 = 0.f, acc10 = 0.f, acc11 = 0.f;
    #pragma unroll 4
    for (int k = 0; k < C_; ++k) {
        float2 f = *(const float2*)&fsmT[k][mq * 2];   // warp broadcast
        float2 w = *(const float2*)&Wt[k][oq * 2];     // conflict-free
        acc00 += f.x * w.x;  acc01 += f.x * w.y;
        acc10 += f.y * w.x;  acc11 += f.y * w.y;
    }

    float2 bb = *(const float2*)(bvec + o0 + oq * 2);
    float2 r0 = make_float2(acc00 + bb.x, acc01 + bb.y);
    float2 r1 = make_float2(acc10 + bb.x, acc11 + bb.y);
    *(float2*)(out + (size_t)(m0 + mq * 2 + 0) * OUTC + o0 + oq * 2) = r0;
    *(float2*)(out + (size_t)(m0 + mq * 2 + 1) * OUTC + o0 + oq * 2) = r1;
}

// ---------------------------------------------------------------------------
extern "C" void kernel_launch(void* const* d_in, const int* in_sizes, int n_in,
                              void* d_out, int out_size) {
    const float* z      = (const float*)d_in[0];   // [B,C,H,W]
    const float* bboxes = (const float*)d_in[1];   // [B,N,4]
    const float* Wm     = (const float*)d_in[2];   // [OUTC,C]
    const float* bvec   = (const float*)d_in[3];   // [OUTC]
    float* out = (float*)d_out;                    // [B,N,OUTC]

    zero_feats_kernel<<<NROI * C_ / (256 * 4), 256>>>();
    dim3 tgrid(HW_ / 128, C_ / 32, B_);            // (32, 4, 16)
    transpose_kernel<<<tgrid, 256>>>(z);
    roi_kernel<<<dim3(NROI, MAXG), 128>>>(bboxes);
    gemm_kernel<<<dim3(NROI / MT, OUTC / OT), 256>>>(Wm, bvec, out);
}